// round 2
// baseline (speedup 1.0000x reference)
#include <cuda_runtime.h>
#include <math.h>

#define Bq   4096
#define Nn   10
#define DIN  32
#define Dd   128
#define PHI  256
#define RHO  128
#define Ll   3
#define EPS  1e-5f

__global__ __launch_bounds__(128)
void gcn_deepset_kernel(
    const float* __restrict__ A,        // [B,N,N]
    const float* __restrict__ X,        // [B,N,DIN]
    const int*   __restrict__ home,     // [B,N]
    const float* __restrict__ We1, const float* __restrict__ be1,
    const float* __restrict__ We2, const float* __restrict__ be2,
    const float* __restrict__ rgcn_w,   // [L,2,D,D]
    const float* __restrict__ rgcn_root,// [L,D,D]
    const float* __restrict__ rgcn_b,   // [L,D]
    const float* __restrict__ l1w, const float* __restrict__ l1b,
    const float* __restrict__ l2w, const float* __restrict__ l2b,
    const float* __restrict__ ln_g, const float* __restrict__ ln_b,
    const float* __restrict__ p1w, const float* __restrict__ p1b,
    const float* __restrict__ p2w, const float* __restrict__ p2b,
    const float* __restrict__ r1w, const float* __restrict__ r1b,
    const float* __restrict__ r2w, const float* __restrict__ r2b,
    float* __restrict__ out)
{
    __shared__ float sH[Nn][Dd];
    __shared__ float sAgg[Nn][Dd];
    __shared__ float sT[Nn][Dd];
    __shared__ float sPhi[Nn][PHI];
    __shared__ float sA[Nn][Nn];
    __shared__ float sX[Nn][DIN];
    __shared__ float sHS[PHI];
    __shared__ float sAWS[PHI];
    __shared__ float sRed[8];
    __shared__ float shm[Nn];

    const int b   = blockIdx.x;
    const int tid = threadIdx.x;   // == d column, 0..127
    const int lane = tid & 31;
    const int wid  = tid >> 5;

    // ---- load per-batch inputs ----
    if (tid < Nn * Nn) ((float*)sA)[tid] = A[b * Nn * Nn + tid];
    for (int idx = tid; idx < Nn * DIN; idx += 128)
        ((float*)sX)[idx] = X[b * Nn * DIN + idx];
    if (tid < Nn) shm[tid] = (float)home[b * Nn + tid];
    __syncthreads();

    // ---- embed: H = relu(X@We1+be1) @ We2 + be2 ----
    {
        float acc[Nn];
        #pragma unroll
        for (int i = 0; i < Nn; ++i) acc[i] = be1[tid];
        #pragma unroll 4
        for (int k = 0; k < DIN; ++k) {
            float w = We1[k * Dd + tid];
            #pragma unroll
            for (int i = 0; i < Nn; ++i) acc[i] += sX[i][k] * w;
        }
        #pragma unroll
        for (int i = 0; i < Nn; ++i) sT[i][tid] = fmaxf(acc[i], 0.f);
    }
    __syncthreads();
    {
        float acc[Nn];
        #pragma unroll
        for (int i = 0; i < Nn; ++i) acc[i] = be2[tid];
        #pragma unroll 4
        for (int k = 0; k < Dd; ++k) {
            float w = We2[k * Dd + tid];
            #pragma unroll
            for (int i = 0; i < Nn; ++i) acc[i] += sT[i][k] * w;
        }
        #pragma unroll
        for (int i = 0; i < Nn; ++i) {
            sH[i][tid] = acc[i];
            sAgg[i][tid] = 0.f;
        }
    }
    __syncthreads();

    // ---- GNN layers ----
    for (int l = 0; l < Ll; ++l) {
        // H += agg  (column-local)
        #pragma unroll
        for (int i = 0; i < Nn; ++i) sH[i][tid] += sAgg[i][tid];

        // per-relation means into sT (mean0), sAgg (mean1)  (column-local)
        #pragma unroll
        for (int j = 0; j < Nn; ++j) {
            float s0 = 0.f, s1 = 0.f;
            int c1 = 0;
            #pragma unroll
            for (int i = 0; i < Nn; ++i) {
                float a = sA[i][j];
                float h = sH[i][tid];
                if (a > 0.f) { s1 += h; c1++; }
                else         { s0 += h; }
            }
            float c0 = (float)(Nn - c1);
            sT[j][tid]   = s0 / fmaxf(c0, 1.f);
            sAgg[j][tid] = s1 / fmaxf((float)c1, 1.f);
        }
        __syncthreads();

        // H2 = mean0@W0 + mean1@W1 + H@root + b
        {
            const float* W0 = rgcn_w + (size_t)(l * 2 + 0) * Dd * Dd;
            const float* W1 = rgcn_w + (size_t)(l * 2 + 1) * Dd * Dd;
            const float* Wr = rgcn_root + (size_t)l * Dd * Dd;
            float acc[Nn];
            float bias = rgcn_b[l * Dd + tid];
            #pragma unroll
            for (int j = 0; j < Nn; ++j) acc[j] = bias;
            #pragma unroll 2
            for (int k = 0; k < Dd; ++k) {
                float w0 = W0[k * Dd + tid];
                float w1 = W1[k * Dd + tid];
                float wr = Wr[k * Dd + tid];
                #pragma unroll
                for (int j = 0; j < Nn; ++j)
                    acc[j] += sT[j][k] * w0 + sAgg[j][k] * w1 + sH[j][k] * wr;
            }
            __syncthreads();           // everyone done reading sT/sAgg
            #pragma unroll
            for (int j = 0; j < Nn; ++j) sT[j][tid] = acc[j];  // sT := H2
        }
        __syncthreads();

        // agg[i] = sum_j H2[j] * |A[i][j]|   (sA broadcast)
        #pragma unroll
        for (int i = 0; i < Nn; ++i) {
            float acc = 0.f;
            #pragma unroll
            for (int j = 0; j < Nn; ++j)
                acc += sT[j][tid] * fabsf(sA[i][j]);
            sAgg[i][tid] = acc;
        }
        __syncthreads();

        // agg = relu(layernorm(agg))
        for (int i = 0; i < Nn; ++i) {
            float x = sAgg[i][tid];
            float s = x, s2 = x * x;
            #pragma unroll
            for (int o = 16; o > 0; o >>= 1) {
                s  += __shfl_down_sync(0xffffffffu, s,  o);
                s2 += __shfl_down_sync(0xffffffffu, s2, o);
            }
            if (lane == 0) { sRed[wid] = s; sRed[4 + wid] = s2; }
            __syncthreads();
            float sum = sRed[0] + sRed[1] + sRed[2] + sRed[3];
            float sq  = sRed[4] + sRed[5] + sRed[6] + sRed[7];
            float mu  = sum * (1.f / Dd);
            float var = sq * (1.f / Dd) - mu * mu;
            float y = (x - mu) * rsqrtf(var + EPS) * ln_g[tid] + ln_b[tid];
            sAgg[i][tid] = fmaxf(y, 0.f);
            __syncthreads();
        }

        // agg = relu(agg@l1w + l1b)  -> sT
        {
            const float* W = l1w + (size_t)l * Dd * Dd;
            float acc[Nn];
            float bias = l1b[l * Dd + tid];
            #pragma unroll
            for (int i = 0; i < Nn; ++i) acc[i] = bias;
            #pragma unroll 4
            for (int k = 0; k < Dd; ++k) {
                float w = W[k * Dd + tid];
                #pragma unroll
                for (int i = 0; i < Nn; ++i) acc[i] += sAgg[i][k] * w;
            }
            __syncthreads();
            #pragma unroll
            for (int i = 0; i < Nn; ++i) sT[i][tid] = fmaxf(acc[i], 0.f);
        }
        __syncthreads();

        // agg = sT@l2w + l2b  -> sAgg
        {
            const float* W = l2w + (size_t)l * Dd * Dd;
            float acc[Nn];
            float bias = l2b[l * Dd + tid];
            #pragma unroll
            for (int i = 0; i < Nn; ++i) acc[i] = bias;
            #pragma unroll 4
            for (int k = 0; k < Dd; ++k) {
                float w = W[k * Dd + tid];
                #pragma unroll
                for (int i = 0; i < Nn; ++i) acc[i] += sT[i][k] * w;
            }
            __syncthreads();
            #pragma unroll
            for (int i = 0; i < Nn; ++i) sAgg[i][tid] = acc[i];
        }
        __syncthreads();
    }

    // ---- H += agg, DeepSet phi ----
    #pragma unroll
    for (int i = 0; i < Nn; ++i) sH[i][tid] += sAgg[i][tid];
    __syncthreads();

    // phi1 = relu(H@p1w + p1b): thread handles cols tid and tid+128
    {
        float acc0[Nn], acc1[Nn];
        float b0 = p1b[tid], b1 = p1b[tid + 128];
        #pragma unroll
        for (int i = 0; i < Nn; ++i) { acc0[i] = b0; acc1[i] = b1; }
        #pragma unroll 2
        for (int k = 0; k < Dd; ++k) {
            float w0 = p1w[k * PHI + tid];
            float w1 = p1w[k * PHI + tid + 128];
            #pragma unroll
            for (int i = 0; i < Nn; ++i) {
                float h = sH[i][k];
                acc0[i] += h * w0;
                acc1[i] += h * w1;
            }
        }
        #pragma unroll
        for (int i = 0; i < Nn; ++i) {
            sPhi[i][tid]       = fmaxf(acc0[i], 0.f);
            sPhi[i][tid + 128] = fmaxf(acc1[i], 0.f);
        }
    }
    __syncthreads();

    // phi2 = relu(phi1@p2w + p2b), then masked sums into sHS/sAWS
    {
        float acc0[Nn], acc1[Nn];
        float b0 = p2b[tid], b1 = p2b[tid + 128];
        #pragma unroll
        for (int i = 0; i < Nn; ++i) { acc0[i] = b0; acc1[i] = b1; }
        #pragma unroll 2
        for (int k = 0; k < PHI; ++k) {
            float w0 = p2w[k * PHI + tid];
            float w1 = p2w[k * PHI + tid + 128];
            #pragma unroll
            for (int i = 0; i < Nn; ++i) {
                float h = sPhi[i][k];
                acc0[i] += h * w0;
                acc1[i] += h * w1;
            }
        }
        float hs0 = 0.f, hs1 = 0.f, as0 = 0.f, as1 = 0.f;
        #pragma unroll
        for (int i = 0; i < Nn; ++i) {
            float m = shm[i];
            float v0 = fmaxf(acc0[i], 0.f);
            float v1 = fmaxf(acc1[i], 0.f);
            hs0 += v0 * m;         as0 += v0 * (1.f - m);
            hs1 += v1 * m;         as1 += v1 * (1.f - m);
        }
        sHS[tid] = hs0;  sHS[tid + 128] = hs1;
        sAWS[tid] = as0; sAWS[tid + 128] = as1;
    }
    __syncthreads();

    // ---- rho(hs) - rho(aws) ----
    {
        float acch = r1b[tid], acca = r1b[tid];
        #pragma unroll 4
        for (int k = 0; k < PHI; ++k) {
            float w = r1w[k * RHO + tid];
            acch += sHS[k] * w;
            acca += sAWS[k] * w;
        }
        float w2 = r2w[tid];
        float ph = fmaxf(acch, 0.f) * w2;
        float pa = fmaxf(acca, 0.f) * w2;
        #pragma unroll
        for (int o = 16; o > 0; o >>= 1) {
            ph += __shfl_down_sync(0xffffffffu, ph, o);
            pa += __shfl_down_sync(0xffffffffu, pa, o);
        }
        if (lane == 0) { sRed[wid] = ph; sRed[4 + wid] = pa; }
        __syncthreads();
        if (tid == 0) {
            float dh = sRed[0] + sRed[1] + sRed[2] + sRed[3];
            float da = sRed[4] + sRed[5] + sRed[6] + sRed[7];
            out[b] = 0.5f + 0.5f * tanhf(dh - da);
        }
    }
}

extern "C" void kernel_launch(void* const* d_in, const int* in_sizes, int n_in,
                              void* d_out, int out_size)
{
    const float* A    = (const float*)d_in[0];
    const float* X    = (const float*)d_in[1];
    const int*   home = (const int*)  d_in[2];
    const float* We1  = (const float*)d_in[3];
    const float* be1  = (const float*)d_in[4];
    const float* We2  = (const float*)d_in[5];
    const float* be2  = (const float*)d_in[6];
    const float* rgw  = (const float*)d_in[7];
    const float* rgr  = (const float*)d_in[8];
    const float* rgb  = (const float*)d_in[9];
    const float* l1w  = (const float*)d_in[10];
    const float* l1b  = (const float*)d_in[11];
    const float* l2w  = (const float*)d_in[12];
    const float* l2b  = (const float*)d_in[13];
    const float* lng  = (const float*)d_in[14];
    const float* lnb  = (const float*)d_in[15];
    const float* p1w  = (const float*)d_in[16];
    const float* p1b  = (const float*)d_in[17];
    const float* p2w  = (const float*)d_in[18];
    const float* p2b  = (const float*)d_in[19];
    const float* r1w  = (const float*)d_in[20];
    const float* r1b  = (const float*)d_in[21];
    const float* r2w  = (const float*)d_in[22];
    const float* r2b  = (const float*)d_in[23];

    gcn_deepset_kernel<<<Bq, 128>>>(
        A, X, home, We1, be1, We2, be2, rgw, rgr, rgb,
        l1w, l1b, l2w, l2b, lng, lnb, p1w, p1b, p2w, p2b,
        r1w, r1b, r2w, r2b, (float*)d_out);
    (void)in_sizes; (void)n_in; (void)out_size; (void)r2b;
}

// round 3
// speedup vs baseline: 1.2115x; 1.2115x over previous
#include <cuda_runtime.h>
#include <math.h>

#define Bq   4096
#define Nn   10
#define DIN  32
#define Dd   128
#define PHId 256
#define RHOd 128
#define Ll   3
#define EPS  1e-5f
#define RP   12          // padded row length (floats) for transposed tiles

typedef unsigned long long u64;

// packed f32x2 helpers
__device__ __forceinline__ u64 pk2(float lo, float hi) {
    u64 r; asm("mov.b64 %0,{%1,%2};" : "=l"(r) : "f"(lo), "f"(hi)); return r;
}
__device__ __forceinline__ void upk2(float& lo, float& hi, u64 v) {
    asm("mov.b64 {%0,%1},%2;" : "=f"(lo), "=f"(hi) : "l"(v));
}
__device__ __forceinline__ u64 fma2(u64 a, u64 b, u64 c) {
    u64 d; asm("fma.rn.f32x2 %0,%1,%2,%3;" : "=l"(d) : "l"(a), "l"(b), "l"(c)); return d;
}

// load 10 floats (5 f32x2 pairs) from a 16B-aligned transposed row
__device__ __forceinline__ void ldp10(const float* __restrict__ r, u64* p) {
    ulonglong2 a = *(const ulonglong2*)r;
    ulonglong2 b = *(const ulonglong2*)(r + 4);
    p[0] = a.x; p[1] = a.y; p[2] = b.x; p[3] = b.y;
    p[4] = *(const u64*)(r + 8);
}
// store 10 floats to a transposed row
__device__ __forceinline__ void stp10(float* __restrict__ r, const float* v) {
    *(float4*)r       = make_float4(v[0], v[1], v[2], v[3]);
    *(float4*)(r + 4) = make_float4(v[4], v[5], v[6], v[7]);
    *(float2*)(r + 8) = make_float2(v[8], v[9]);
}
// unpack 5 pairs to 10 floats
__device__ __forceinline__ void upk10(float* v, const u64* p) {
    #pragma unroll
    for (int q = 0; q < 5; ++q) upk2(v[2*q], v[2*q+1], p[q]);
}

// shared pool layout (floats), all rows 48B so 16B-aligned
#define HT_OFF   0                    // sHt  [128][12]
#define AG_OFF   (128*RP)             // sAgg [128][12]
#define TT_OFF   (2*128*RP)           // sTt  [128][12]
#define M0_OFF   (3*128*RP)           // sM0  [128][12]   (aliases sXt[32][12], sPhi lower half)
#define M1_OFF   (4*128*RP)           // sM1  [128][12]   (aliases sPhi upper half)
#define POOL_SZ  (5*128*RP)
#define PHI_OFF  M0_OFF               // sPhi [256][12]

__global__ __launch_bounds__(128)
void gcn_deepset_kernel(
    const float* __restrict__ A, const float* __restrict__ X,
    const int* __restrict__ home,
    const float* __restrict__ We1, const float* __restrict__ be1,
    const float* __restrict__ We2, const float* __restrict__ be2,
    const float* __restrict__ rgcn_w, const float* __restrict__ rgcn_root,
    const float* __restrict__ rgcn_b,
    const float* __restrict__ l1w, const float* __restrict__ l1b,
    const float* __restrict__ l2w, const float* __restrict__ l2b,
    const float* __restrict__ ln_g, const float* __restrict__ ln_b,
    const float* __restrict__ p1w, const float* __restrict__ p1b,
    const float* __restrict__ p2w, const float* __restrict__ p2b,
    const float* __restrict__ r1w, const float* __restrict__ r1b,
    const float* __restrict__ r2w, const float* __restrict__ r2b,
    float* __restrict__ out)
{
    __shared__ __align__(16) float pool[POOL_SZ];
    __shared__ __align__(16) float sAbs[Nn * RP];      // |A| rows, padded
    __shared__ __align__(16) float2 sCoef[Nn * RP];    // (coef0, coef1) per (j,i)
    __shared__ float sRawA[Nn * Nn];
    __shared__ __align__(16) float sHS[PHId];
    __shared__ __align__(16) float sAWS[PHId];
    __shared__ float sMu[Nn], sRstd[Nn], shm[Nn], sRed[8];

    const int b    = blockIdx.x;
    const int tid  = threadIdx.x;          // output column 0..127
    const int lane = tid & 31;
    const int wid  = tid >> 5;

    // ---- load per-batch inputs ----
    if (tid < Nn * Nn) {
        float v = A[b * Nn * Nn + tid];
        sRawA[tid] = v;
        sAbs[(tid / Nn) * RP + (tid % Nn)] = fabsf(v);
    }
    for (int idx = tid; idx < Nn * DIN; idx += 128) {     // X transposed -> M0 region
        int i = idx / DIN, k = idx % DIN;
        pool[M0_OFF + k * RP + i] = X[b * Nn * DIN + idx];
    }
    if (tid < Nn) shm[tid] = (float)home[b * Nn + tid];
    __syncthreads();

    // layer-invariant relation coefficients (10 threads)
    if (tid < Nn) {
        int j = tid, c1 = 0;
        #pragma unroll
        for (int i = 0; i < Nn; ++i) c1 += (sRawA[i * Nn + j] > 0.f);
        float r1c = 1.f / fmaxf((float)c1, 1.f);
        float r0c = 1.f / fmaxf((float)(Nn - c1), 1.f);
        #pragma unroll
        for (int i = 0; i < Nn; ++i) {
            bool m1 = sRawA[i * Nn + j] > 0.f;
            sCoef[j * RP + i] = make_float2(m1 ? 0.f : r0c, m1 ? r1c : 0.f);
        }
    }

    const float gT = ln_g[tid], bT = ln_b[tid];
    float h[Nn], aggR[Nn], v10[Nn];
    u64 acc[5];

    // ---- embed stage 1: relu(X@We1+be1) -> TT (transposed) ----
    {
        u64 bb = pk2(be1[tid], be1[tid]);
        #pragma unroll
        for (int q = 0; q < 5; ++q) acc[q] = bb;
        const float* W = We1 + tid;
        #pragma unroll 8
        for (int k = 0; k < DIN; ++k) {
            float w = W[k * Dd];
            u64 wp = pk2(w, w), xp[5];
            ldp10(&pool[M0_OFF + k * RP], xp);
            #pragma unroll
            for (int q = 0; q < 5; ++q) acc[q] = fma2(xp[q], wp, acc[q]);
        }
        upk10(v10, acc);
        #pragma unroll
        for (int i = 0; i < Nn; ++i) v10[i] = fmaxf(v10[i], 0.f);
        stp10(&pool[TT_OFF + tid * RP], v10);
    }
    __syncthreads();

    // ---- embed stage 2: (T@We2+be2) -> h regs ----
    {
        u64 bb = pk2(be2[tid], be2[tid]);
        #pragma unroll
        for (int q = 0; q < 5; ++q) acc[q] = bb;
        const float* W = We2 + tid;
        #pragma unroll 4
        for (int k = 0; k < Dd; ++k) {
            float w = W[k * Dd];
            u64 wp = pk2(w, w), xp[5];
            ldp10(&pool[TT_OFF + k * RP], xp);
            #pragma unroll
            for (int q = 0; q < 5; ++q) acc[q] = fma2(xp[q], wp, acc[q]);
        }
        upk10(h, acc);
        #pragma unroll
        for (int i = 0; i < Nn; ++i) aggR[i] = 0.f;
    }
    __syncthreads();

    // ---- GNN layers ----
    for (int l = 0; l < Ll; ++l) {
        // residual + publish H (transposed row owned by this thread)
        #pragma unroll
        for (int i = 0; i < Nn; ++i) h[i] += aggR[i];
        stp10(&pool[HT_OFF + tid * RP], h);

        // per-relation means (register h ⊗ precomputed coefs), publish
        {
            u64 hp[Nn];
            #pragma unroll
            for (int i = 0; i < Nn; ++i) hp[i] = pk2(h[i], h[i]);
            float m0v[Nn], m1v[Nn];
            #pragma unroll
            for (int j = 0; j < Nn; ++j) {
                u64 mp = pk2(0.f, 0.f);
                const u64* cp = (const u64*)&sCoef[j * RP];
                #pragma unroll
                for (int i = 0; i < Nn; ++i) mp = fma2(cp[i], hp[i], mp);
                upk2(m0v[j], m1v[j], mp);
            }
            stp10(&pool[M0_OFF + tid * RP], m0v);
            stp10(&pool[M1_OFF + tid * RP], m1v);
        }
        __syncthreads();   // A: H/M0/M1 visible

        // H2 = mean0@W0 + mean1@W1 + H@root + b   (kept in regs, packed pairs over j)
        {
            const float* W0 = rgcn_w    + (size_t)(l * 2 + 0) * Dd * Dd + tid;
            const float* W1 = rgcn_w    + (size_t)(l * 2 + 1) * Dd * Dd + tid;
            const float* Wr = rgcn_root + (size_t)l * Dd * Dd + tid;
            float bias = rgcn_b[l * Dd + tid];
            u64 bb = pk2(bias, bias);
            #pragma unroll
            for (int q = 0; q < 5; ++q) acc[q] = bb;
            #pragma unroll 2
            for (int k = 0; k < Dd; ++k) {
                float w0 = W0[k * Dd], w1 = W1[k * Dd], wr = Wr[k * Dd];
                u64 wp0 = pk2(w0, w0), wp1 = pk2(w1, w1), wpr = pk2(wr, wr);
                u64 p0[5], p1[5], ph[5];
                ldp10(&pool[M0_OFF + k * RP], p0);
                ldp10(&pool[M1_OFF + k * RP], p1);
                ldp10(&pool[HT_OFF + k * RP], ph);
                #pragma unroll
                for (int q = 0; q < 5; ++q)
                    acc[q] = fma2(p0[q], wp0, fma2(p1[q], wp1, fma2(ph[q], wpr, acc[q])));
            }
        }

        // agg[i] = sum_j H2[j] * |A[i][j]|  (packed over j pairs, from regs)
        #pragma unroll
        for (int i = 0; i < Nn; ++i) {
            u64 ap = pk2(0.f, 0.f), aa[5];
            ldp10(&sAbs[i * RP], aa);
            #pragma unroll
            for (int q = 0; q < 5; ++q) ap = fma2(acc[q], aa[q], ap);
            float lo, hi; upk2(lo, hi, ap);
            aggR[i] = lo + hi;
        }
        stp10(&pool[AG_OFF + tid * RP], aggR);
        __syncthreads();   // B: raw agg visible

        // LN stats: warp w handles rows w, w+4, w+8
        for (int r = wid; r < Nn; r += 4) {
            float s = 0.f, q = 0.f;
            #pragma unroll
            for (int u = 0; u < 4; ++u) {
                float x = pool[AG_OFF + (lane + 32 * u) * RP + r];
                s += x; q += x * x;
            }
            #pragma unroll
            for (int o = 16; o > 0; o >>= 1) {
                s += __shfl_xor_sync(0xffffffffu, s, o);
                q += __shfl_xor_sync(0xffffffffu, q, o);
            }
            if (lane == 0) {
                float mu = s * (1.f / Dd);
                float var = q * (1.f / Dd) - mu * mu;
                sMu[r] = mu; sRstd[r] = rsqrtf(var + EPS);
            }
        }
        __syncthreads();   // C: stats visible

        // normalize + relu, publish
        #pragma unroll
        for (int i = 0; i < Nn; ++i) {
            float y = (aggR[i] - sMu[i]) * sRstd[i] * gT + bT;
            aggR[i] = fmaxf(y, 0.f);
        }
        stp10(&pool[AG_OFF + tid * RP], aggR);
        __syncthreads();   // D

        // l1: relu(agg@W+b) -> TT
        {
            const float* W = l1w + (size_t)l * Dd * Dd + tid;
            float bias = l1b[l * Dd + tid];
            u64 bb = pk2(bias, bias);
            #pragma unroll
            for (int q = 0; q < 5; ++q) acc[q] = bb;
            #pragma unroll 4
            for (int k = 0; k < Dd; ++k) {
                float w = W[k * Dd];
                u64 wp = pk2(w, w), xp[5];
                ldp10(&pool[AG_OFF + k * RP], xp);
                #pragma unroll
                for (int q = 0; q < 5; ++q) acc[q] = fma2(xp[q], wp, acc[q]);
            }
            upk10(v10, acc);
            #pragma unroll
            for (int i = 0; i < Nn; ++i) v10[i] = fmaxf(v10[i], 0.f);
            stp10(&pool[TT_OFF + tid * RP], v10);
        }
        __syncthreads();   // E

        // l2: (t@W+b) -> aggR regs
        {
            const float* W = l2w + (size_t)l * Dd * Dd + tid;
            float bias = l2b[l * Dd + tid];
            u64 bb = pk2(bias, bias);
            #pragma unroll
            for (int q = 0; q < 5; ++q) acc[q] = bb;
            #pragma unroll 4
            for (int k = 0; k < Dd; ++k) {
                float w = W[k * Dd];
                u64 wp = pk2(w, w), xp[5];
                ldp10(&pool[TT_OFF + k * RP], xp);
                #pragma unroll
                for (int q = 0; q < 5; ++q) acc[q] = fma2(xp[q], wp, acc[q]);
            }
            upk10(aggR, acc);
        }
    }

    // ---- final residual, publish H ----
    #pragma unroll
    for (int i = 0; i < Nn; ++i) h[i] += aggR[i];
    stp10(&pool[HT_OFF + tid * RP], h);
    __syncthreads();

    // ---- phi1: relu(H@p1w+p1b), cols tid and tid+128 -> PHI region ----
    {
        u64 a0[5], a1[5];
        u64 b0 = pk2(p1b[tid], p1b[tid]), b1 = pk2(p1b[tid + 128], p1b[tid + 128]);
        #pragma unroll
        for (int q = 0; q < 5; ++q) { a0[q] = b0; a1[q] = b1; }
        const float* W = p1w + tid;
        #pragma unroll 2
        for (int k = 0; k < Dd; ++k) {
            float w0 = W[k * PHId], w1 = W[k * PHId + 128];
            u64 wp0 = pk2(w0, w0), wp1 = pk2(w1, w1), xp[5];
            ldp10(&pool[HT_OFF + k * RP], xp);
            #pragma unroll
            for (int q = 0; q < 5; ++q) {
                a0[q] = fma2(xp[q], wp0, a0[q]);
                a1[q] = fma2(xp[q], wp1, a1[q]);
            }
        }
        float t0[Nn], t1[Nn];
        upk10(t0, a0); upk10(t1, a1);
        #pragma unroll
        for (int i = 0; i < Nn; ++i) { t0[i] = fmaxf(t0[i], 0.f); t1[i] = fmaxf(t1[i], 0.f); }
        stp10(&pool[PHI_OFF + tid * RP], t0);
        stp10(&pool[PHI_OFF + (tid + 128) * RP], t1);
    }
    __syncthreads();

    // ---- phi2 + masked sums ----
    {
        u64 a0[5], a1[5];
        u64 b0 = pk2(p2b[tid], p2b[tid]), b1 = pk2(p2b[tid + 128], p2b[tid + 128]);
        #pragma unroll
        for (int q = 0; q < 5; ++q) { a0[q] = b0; a1[q] = b1; }
        const float* W = p2w + tid;
        #pragma unroll 2
        for (int k = 0; k < PHId; ++k) {
            float w0 = W[k * PHId], w1 = W[k * PHId + 128];
            u64 wp0 = pk2(w0, w0), wp1 = pk2(w1, w1), xp[5];
            ldp10(&pool[PHI_OFF + k * RP], xp);
            #pragma unroll
            for (int q = 0; q < 5; ++q) {
                a0[q] = fma2(xp[q], wp0, a0[q]);
                a1[q] = fma2(xp[q], wp1, a1[q]);
            }
        }
        float t0[Nn], t1[Nn];
        upk10(t0, a0); upk10(t1, a1);
        float hs0 = 0.f, hs1 = 0.f, as0 = 0.f, as1 = 0.f;
        #pragma unroll
        for (int i = 0; i < Nn; ++i) {
            float m = shm[i];
            float u0 = fmaxf(t0[i], 0.f), u1 = fmaxf(t1[i], 0.f);
            hs0 += u0 * m; as0 += u0 * (1.f - m);
            hs1 += u1 * m; as1 += u1 * (1.f - m);
        }
        sHS[tid] = hs0;  sHS[tid + 128] = hs1;
        sAWS[tid] = as0; sAWS[tid + 128] = as1;
    }
    __syncthreads();

    // ---- rho(hs) - rho(aws) ----
    {
        float acch = r1b[tid], acca = r1b[tid];
        const float* W = r1w + tid;
        #pragma unroll 4
        for (int k = 0; k < PHId; k += 4) {
            float4 hv = *(const float4*)&sHS[k];
            float4 av = *(const float4*)&sAWS[k];
            float w0 = W[k * RHOd], w1 = W[(k + 1) * RHOd];
            float w2 = W[(k + 2) * RHOd], w3 = W[(k + 3) * RHOd];
            acch += hv.x * w0 + hv.y * w1 + hv.z * w2 + hv.w * w3;
            acca += av.x * w0 + av.y * w1 + av.z * w2 + av.w * w3;
        }
        float w2v = r2w[tid];
        float ph = fmaxf(acch, 0.f) * w2v;
        float pa = fmaxf(acca, 0.f) * w2v;
        #pragma unroll
        for (int o = 16; o > 0; o >>= 1) {
            ph += __shfl_down_sync(0xffffffffu, ph, o);
            pa += __shfl_down_sync(0xffffffffu, pa, o);
        }
        if (lane == 0) { sRed[wid] = ph; sRed[4 + wid] = pa; }
        __syncthreads();
        if (tid == 0) {
            float dh = sRed[0] + sRed[1] + sRed[2] + sRed[3];
            float da = sRed[4] + sRed[5] + sRed[6] + sRed[7];
            out[b] = 0.5f + 0.5f * tanhf(dh - da);
        }
    }
}

extern "C" void kernel_launch(void* const* d_in, const int* in_sizes, int n_in,
                              void* d_out, int out_size)
{
    const float* A    = (const float*)d_in[0];
    const float* X    = (const float*)d_in[1];
    const int*   home = (const int*)  d_in[2];
    const float* We1  = (const float*)d_in[3];
    const float* be1  = (const float*)d_in[4];
    const float* We2  = (const float*)d_in[5];
    const float* be2  = (const float*)d_in[6];
    const float* rgw  = (const float*)d_in[7];
    const float* rgr  = (const float*)d_in[8];
    const float* rgb  = (const float*)d_in[9];
    const float* l1w  = (const float*)d_in[10];
    const float* l1b  = (const float*)d_in[11];
    const float* l2w  = (const float*)d_in[12];
    const float* l2b  = (const float*)d_in[13];
    const float* lng  = (const float*)d_in[14];
    const float* lnb  = (const float*)d_in[15];
    const float* p1w  = (const float*)d_in[16];
    const float* p1b  = (const float*)d_in[17];
    const float* p2w  = (const float*)d_in[18];
    const float* p2b  = (const float*)d_in[19];
    const float* r1w  = (const float*)d_in[20];
    const float* r1b  = (const float*)d_in[21];
    const float* r2w  = (const float*)d_in[22];
    const float* r2b  = (const float*)d_in[23];

    gcn_deepset_kernel<<<Bq, 128>>>(
        A, X, home, We1, be1, We2, be2, rgw, rgr, rgb,
        l1w, l1b, l2w, l2b, lng, lnb, p1w, p1b, p2w, p2b,
        r1w, r1b, r2w, r2b, (float*)d_out);
    (void)in_sizes; (void)n_in; (void)out_size; (void)r2b;
}